// round 17
// baseline (speedup 1.0000x reference)
#include <cuda_runtime.h>
#include <cstdint>

// SepKANLayer1D: per-token KAN edge-spline layer.
// x: (4, 8, 65536) f32, w: (4, 640, 65536) f32, out: (4, 8, 65536) f32.
// PER-WARP cooperative-tile streaming: each warp stages the 16 coef rows for
// its own 32 tokens (2 KB/stage, double-buffered) via 16B cp.async.cg, and
// synchronizes only at warp scope (wait_group + __syncwarp) -- NO
// __syncthreads, so the 4 warp-pipelines per CTA run fully decoupled and
// per-warp stage jitter no longer gates the whole CTA.
// Consume: dynamic 4-of-8 gather (only bases m..m+3 nonzero; bank = lane ->
// conflict-free). 4 threads/token (OH=2 via grid.y).

#define IN_C   8
#define OUT_C  8
#define NB     8
#define OH     2
#define NTOK   65536
#define WSIZE  640
#define NROWS  16               // coef rows staged per iteration
#define TPB    128
#define NWARP  4

__device__ __forceinline__ void cp16(unsigned int smem_dst, const float* gptr) {
    asm volatile("cp.async.cg.shared.global [%0], [%1], 16;\n"
                 :: "r"(smem_dst), "l"(gptr));
}
__device__ __forceinline__ void cp_commit() {
    asm volatile("cp.async.commit_group;\n" ::: "memory");
}
template <int N>
__device__ __forceinline__ void cp_wait() {
    asm volatile("cp.async.wait_group %0;\n" :: "n"(N) : "memory");
}

__global__ __launch_bounds__(TPB, 14)   // 16 KB smem/CTA, reg cap 36
void sepkan_kernel(const float* __restrict__ x,
                   const float* __restrict__ w,
                   float* __restrict__ out) {
    __shared__ float buf[2][NWARP][NROWS][32];   // 2 x 8 KB

    const int tid  = threadIdx.x;
    const int lane = tid & 31;
    const int wid  = tid >> 5;
    const int ob = blockIdx.y * OH;          // 0,2,4,6
    const int b  = blockIdx.x >> 9;          // 512 token-blocks per batch
    const int n0 = (blockIdx.x & 511) * TPB; // token base of this CTA
    const int n  = n0 + tid;                 // this thread's token

    const float* xp = x + (size_t)b * IN_C * NTOK + n;
    const float* wp = w + (size_t)b * WSIZE * NTOK + n;       // per-thread (uw/rw)
    // this warp's staging source base: warp tokens start at n0 + wid*32;
    // lane l covers row (l>>3) within each 4-row group, chunk (l&7)*16B.
    const float* wsrc = w + (size_t)b * WSIZE * NTOK + n0 + wid * 32 + (lane & 7) * 4;
    const int rsub = lane >> 3;              // 0..3: row-within-group

    // stage one iteration's 16 coef rows (for this warp's 32 tokens) into
    // buffer s: 4 LDGSTS.16 per lane, one commit group.
    auto issue = [&](int i, int s) {
#pragma unroll
        for (int q = 0; q < 4; ++q) {
            const int r = 4 * q + rsub;      // local coef row 0..15
            const int gr = i * OUT_C * NB + ob * NB + r;
            const unsigned int dst =
                (unsigned int)__cvta_generic_to_shared(&buf[s][wid][r][(lane & 7) * 4]);
            cp16(dst, wsrc + (size_t)gr * NTOK);
        }
        cp_commit();
    };

    float acc0 = 0.0f, acc1 = 0.0f;
    float xi_next = __ldg(xp);               // prefetch channel 0's x

    issue(0, 0);                             // prologue

#pragma unroll 1
    for (int i = 0; i < IN_C; ++i) {
        const int s = i & 1;
        if (i + 1 < IN_C) issue(i + 1, s ^ 1);

        // uw/rw direct streaming loads for this iteration (batched early)
        const float* wu = wp + (size_t)(IN_C * OUT_C * NB + i * OUT_C + ob) * NTOK;
        const float* wr = wp + (size_t)(IN_C * OUT_C * NB + IN_C * OUT_C + i * OUT_C + ob) * NTOK;
        const float u0 = __ldcs(wu);
        const float u1 = __ldcs(wu + NTOK);
        const float r0 = __ldcs(wr);
        const float r1 = __ldcs(wr + NTOK);

        const float xi = xi_next;
        if (i + 1 < IN_C) xi_next = __ldg(xp + (i + 1) * NTOK);

        // ---- closed-form uniform cubic B-spline (load-independent shim) ----
        // m = clamp(floor(5x),0,4), u = 5x-m. Nonzero bases m..m+3:
        //   (1-u)^3/6, (3u^3-6u^2+4)/6, (-3u^3+3u^2+3u+1)/6, u^3/6
        int m = (int)(5.0f * xi);
        m = (m < 0) ? 0 : (m > 4 ? 4 : m);
        const float uu = 5.0f * xi - (float)m;
        const float vv = 1.0f - uu;
        const float uu2 = uu * uu, uu3 = uu2 * uu;
        float bw[4];
        bw[0] = vv * vv * vv * (1.0f / 6.0f);
        bw[1] = (3.0f * uu3 - 6.0f * uu2 + 4.0f) * (1.0f / 6.0f);
        bw[2] = (-3.0f * uu3 + 3.0f * uu2 + 3.0f * uu + 1.0f) * (1.0f / 6.0f);
        bw[3] = uu3 * (1.0f / 6.0f);

        const float sx = xi / (1.0f + __expf(-xi));   // silu

        // ---- warp-scope stage handoff: each lane waits on ITS groups, then
        // __syncwarp orders visibility of all lanes' staged data.        ----
        if (i + 1 < IN_C) cp_wait<1>(); else cp_wait<0>();
        __syncwarp();

        // dynamic 4-of-8 gather: rows m..m+3 (o=ob) and 8+m..8+m+3 (o=ob+1).
        // smem bank = lane regardless of m -> conflict-free.
        const float* sv = &buf[s][wid][0][lane];
        float sp0 = 0.0f, sp1 = 0.0f;
#pragma unroll
        for (int j = 0; j < 4; ++j) {
            sp0 = fmaf(bw[j], sv[(m + j) * 32],      sp0);
            sp1 = fmaf(bw[j], sv[(NB + m + j) * 32], sp1);
        }
        acc0 = fmaf(u0, sp0, acc0);
        acc1 = fmaf(u1, sp1, acc1);
        acc0 = fmaf(sx, r0, acc0);
        acc1 = fmaf(sx, r1, acc1);

        __syncwarp();                        // reads of s done before i+2 overwrites
    }

    float* yp = out + ((size_t)b * OUT_C + ob) * NTOK + n;
    __stcs(yp, acc0);
    __stcs(yp + NTOK, acc1);
}

extern "C" void kernel_launch(void* const* d_in, const int* in_sizes, int n_in,
                              void* d_out, int out_size) {
    const float* x = (const float*)d_in[0];   // (4, 8, 65536)
    const float* w = (const float*)d_in[1];   // (4, 640, 65536)
    float* out = (float*)d_out;               // (4, 8, 65536)

    const int total = 4 * NTOK;               // 262144 tokens
    dim3 grid(total / TPB, OUT_C / OH);       // (2048, 4)
    sepkan_kernel<<<grid, TPB>>>(x, w, out);
}